// round 1
// baseline (speedup 1.0000x reference)
#include <cuda_runtime.h>

// Problem constants (fixed by the reference):
//   N_NODES = 2048, N_ELEMS = 4096
//   Output: (N + 2E) x (2E + N) = 10240 x 10240 fp32
#define NN 2048
#define EE 4096
#define WW (2 * EE + NN)   // 10240
#define W4 (WW / 4)        // 2560

// ---------------------------------------------------------------------------
// Fill kernel: writes the whole output with float4 stores, EXCEPT the -M^T
// block (rows [N, N+E), cols [2E, W)) which is written by the transpose
// kernel for coalesced access.
// ---------------------------------------------------------------------------
__global__ void __launch_bounds__(256) fill_kernel(
    const float* __restrict__ M,
    const float* __restrict__ params,
    const int* __restrict__ kinds,
    float* __restrict__ out)
{
    const int row = blockIdx.y;
    const int c4  = blockIdx.x * blockDim.x + threadIdx.x;   // 0 .. W4-1
    if (c4 >= W4) return;
    const int col = c4 * 4;

    float4 v = make_float4(0.f, 0.f, 0.f, 0.f);

    if (row < NN) {
        // kcl rows: [ M | 0 ]
        if (col < EE) {
            v = reinterpret_cast<const float4*>(M)[row * (EE / 4) + c4];
        }
    } else if (row < NN + EE) {
        // kvl rows: [ 0 | I_E | -M^T ]
        if (col >= 2 * EE) return;   // -M^T handled by transpose kernel
        const int r = row - NN;
        if (col >= EE) {
            const int d = EE + r;    // column of the identity 1
            if (d >= col && d < col + 4) {
                reinterpret_cast<float*>(&v)[d - col] = 1.0f;
            }
        }
        // col < EE -> zeros (already)
    } else {
        // elem rows: z diag at col=pos, y diag at col=E+pos, zeros elsewhere
        const int pos = row - NN - EE;
        const int yc = EE + pos;
        if (pos >= col && pos < col + 4) {
            const float p = params[pos];
            const int   k = kinds[pos];
            float z = 0.0f;
            if (k == 0)                       z = -p;   // R
            else if (k == 2)                  z = 1.0f; // VC
            else if (k == 3 && !(p > 0.0f))   z = 1.0f; // SW off
            reinterpret_cast<float*>(&v)[pos - col] = z;
        }
        if (yc >= col && yc < col + 4) {
            const float p = params[pos];
            const int   k = kinds[pos];
            const float y = (k == 0 || k == 1 || (k == 3 && p > 0.0f)) ? 1.0f : 0.0f;
            reinterpret_cast<float*>(&v)[yc - col] = y;
        }
    }

    reinterpret_cast<float4*>(out)[row * W4 + c4] = v;
}

// ---------------------------------------------------------------------------
// Tiled transpose: out[N + e][2E + n] = -M[n][e]
// 32x32 tiles via shared memory (33-wide to kill bank conflicts); both the
// global read of M and the global write of the output are fully coalesced.
// ---------------------------------------------------------------------------
__global__ void __launch_bounds__(256) transpose_neg_kernel(
    const float* __restrict__ M,
    float* __restrict__ out)
{
    __shared__ float tile[32][33];

    const int e0 = blockIdx.x * 32;   // column tile in M (row tile in output)
    const int n0 = blockIdx.y * 32;   // row tile in M    (col tile in output)
    const int tx = threadIdx.x;       // 0..31
    const int ty = threadIdx.y;       // 0..7

    #pragma unroll
    for (int i = 0; i < 32; i += 8) {
        tile[ty + i][tx] = M[(n0 + ty + i) * EE + (e0 + tx)];
    }
    __syncthreads();

    #pragma unroll
    for (int i = 0; i < 32; i += 8) {
        out[(NN + e0 + ty + i) * WW + 2 * EE + (n0 + tx)] = -tile[tx][ty + i];
    }
}

// ---------------------------------------------------------------------------
// Launch
// ---------------------------------------------------------------------------
extern "C" void kernel_launch(void* const* d_in, const int* in_sizes, int n_in,
                              void* d_out, int out_size)
{
    const float* M      = (const float*)d_in[0];
    const float* params = (const float*)d_in[1];
    const int*   kinds  = (const int*)d_in[2];
    float*       out    = (float*)d_out;

    (void)in_sizes; (void)n_in; (void)out_size;

    // Fill everything except -M^T block
    {
        dim3 block(256, 1, 1);
        dim3 grid((W4 + 255) / 256, WW, 1);   // 10 x 10240 blocks
        fill_kernel<<<grid, block>>>(M, params, kinds, out);
    }

    // -M^T block (independent region; same stream, no sync needed for
    // correctness since regions are disjoint)
    {
        dim3 block(32, 8, 1);
        dim3 grid(EE / 32, NN / 32, 1);       // 128 x 64 blocks
        transpose_neg_kernel<<<grid, block>>>(M, out);
    }
}

// round 2
// speedup vs baseline: 1.0360x; 1.0360x over previous
#include <cuda_runtime.h>

// Problem constants (fixed by the reference):
//   N_NODES = 2048, N_ELEMS = 4096
//   Output: (N + 2E) x (2E + N) = 10240 x 10240 fp32
#define NN 2048
#define EE 4096
#define WW (2 * EE + NN)   // 10240
#define W4 (WW / 4)        // 2560

// Fill: 10 column-blocks (of 256 thr * 4 floats = 1024 cols) per row, all rows.
#define FILL_BLOCKS_PER_ROW 10
#define NUM_FILL_BLOCKS (FILL_BLOCKS_PER_ROW * WW)          // 102400
// Transpose: 32x32 tiles over the E x N (-M^T) block
#define TP_TILES_X (EE / 32)                                 // 128 (e tiles)
#define TP_TILES_Y (NN / 32)                                 // 64  (n tiles)
#define NUM_TP_BLOCKS (TP_TILES_X * TP_TILES_Y)              // 8192
#define TOTAL_BLOCKS (NUM_FILL_BLOCKS + NUM_TP_BLOCKS)       // 110592

// ---------------------------------------------------------------------------
// Fused kernel: one launch covers the entire output.
//   blocks [0, NUM_FILL_BLOCKS)            -> row-strip fill (float4 stores)
//   blocks [NUM_FILL_BLOCKS, TOTAL_BLOCKS) -> 32x32 -M^T transpose tiles
// Regions are disjoint: fill blocks skip the -M^T block entirely.
// ---------------------------------------------------------------------------
__global__ void __launch_bounds__(256) fused_kernel(
    const float* __restrict__ M,
    const float* __restrict__ params,
    const int* __restrict__ kinds,
    float* __restrict__ out)
{
    const int bid = blockIdx.x;
    const int tid = threadIdx.x;

    if (bid < NUM_FILL_BLOCKS) {
        // ------------------------------------------------------------------
        // FILL path
        // ------------------------------------------------------------------
        const int row  = bid / FILL_BLOCKS_PER_ROW;
        const int cblk = bid - row * FILL_BLOCKS_PER_ROW;
        const int c4   = cblk * 256 + tid;          // 0 .. W4-1
        const int col  = c4 * 4;

        float4 v = make_float4(0.f, 0.f, 0.f, 0.f);

        if (row < NN) {
            // kcl rows: [ M | 0 ]
            if (col < EE) {
                v = reinterpret_cast<const float4*>(M)[row * (EE / 4) + c4];
            }
        } else if (row < NN + EE) {
            // kvl rows: [ 0 | I_E | -M^T ]
            if (col >= 2 * EE) return;   // -M^T written by transpose blocks
            const int r = row - NN;
            if (col >= EE) {
                const int d = EE + r;    // column of the identity 1
                if (d >= col && d < col + 4) {
                    reinterpret_cast<float*>(&v)[d - col] = 1.0f;
                }
            }
        } else {
            // elem rows: z diag at col=pos, y diag at col=E+pos
            const int pos = row - NN - EE;
            const int yc  = EE + pos;
            if (pos >= col && pos < col + 4) {
                const float p = params[pos];
                const int   k = kinds[pos];
                float z = 0.0f;
                if (k == 0)                      z = -p;   // R
                else if (k == 2)                 z = 1.0f; // VC
                else if (k == 3 && !(p > 0.0f))  z = 1.0f; // SW off
                reinterpret_cast<float*>(&v)[pos - col] = z;
            }
            if (yc >= col && yc < col + 4) {
                const float p = params[pos];
                const int   k = kinds[pos];
                const float y = (k == 0 || k == 1 || (k == 3 && p > 0.0f)) ? 1.0f : 0.0f;
                reinterpret_cast<float*>(&v)[yc - col] = y;
            }
        }

        reinterpret_cast<float4*>(out)[row * W4 + c4] = v;
    } else {
        // ------------------------------------------------------------------
        // TRANSPOSE path: out[NN + e][2*EE + n] = -M[n][e]
        // 32x32 tile via shared memory; coalesced float4 reads of M and
        // float4 writes of out; 33-wide padding -> conflict-free LDS.
        // ------------------------------------------------------------------
        __shared__ float tile[32][33];   // [n_local][e_local]

        const int t  = bid - NUM_FILL_BLOCKS;
        const int et = t % TP_TILES_X;
        const int nt = t / TP_TILES_X;
        const int e0 = et * 32;
        const int n0 = nt * 32;

        // Load: 256 threads, each a float4 from M (32 rows x 8 float4/row)
        {
            const int lrow = tid >> 3;          // 0..31  (n_local)
            const int lc4  = tid & 7;           // 0..7   (e_local/4)
            const float4 m4 = reinterpret_cast<const float4*>(
                M + (n0 + lrow) * EE + e0)[lc4];
            tile[lrow][lc4 * 4 + 0] = m4.x;
            tile[lrow][lc4 * 4 + 1] = m4.y;
            tile[lrow][lc4 * 4 + 2] = m4.z;
            tile[lrow][lc4 * 4 + 3] = m4.w;
        }
        __syncthreads();

        // Store: thread -> one float4 of output. orow = e_local, oc4 = n_local/4
        {
            const int orow = tid >> 3;          // 0..31  (e_local)
            const int oc4  = tid & 7;           // 0..7
            const int nl   = oc4 * 4;
            float4 v;
            v.x = -tile[nl + 0][orow];
            v.y = -tile[nl + 1][orow];
            v.z = -tile[nl + 2][orow];
            v.w = -tile[nl + 3][orow];
            reinterpret_cast<float4*>(
                out + (NN + e0 + orow) * WW + 2 * EE + n0)[oc4] = v;
        }
    }
}

// ---------------------------------------------------------------------------
// Launch
// ---------------------------------------------------------------------------
extern "C" void kernel_launch(void* const* d_in, const int* in_sizes, int n_in,
                              void* d_out, int out_size)
{
    const float* M      = (const float*)d_in[0];
    const float* params = (const float*)d_in[1];
    const int*   kinds  = (const int*)d_in[2];
    float*       out    = (float*)d_out;

    (void)in_sizes; (void)n_in; (void)out_size;

    fused_kernel<<<TOTAL_BLOCKS, 256>>>(M, params, kinds, out);
}